// round 2
// baseline (speedup 1.0000x reference)
#include <cuda_runtime.h>
#include <math.h>

#define BB 16      // batch
#define NR 512     // real points
#define NP 384     // padding points (N1 = M1)
#define NT 896     // total points per side
#define DD 256     // feature dim

// ---------------- scratch (static device globals; no dynamic alloc) ----------------
__device__ float d_f1n[BB*NT*DD];     // normalized f1 = [x1; x3]
__device__ float d_f2n[BB*NT*DD];     // normalized f2 = [x2; x4]
__device__ float d_C [BB*NT*NT];      // S then C (in-place)
__device__ float d_CT[BB*NT*NT];      // C transposed
__device__ float d_sr[BB*NT];         // row sums of S
__device__ float d_sc[BB*NT];         // col sums of S
__device__ float d_fv[BB*NT];         // f_ba
__device__ float d_gv[BB*NT];         // g_ab
__device__ float d_ftA[BB*NT];        // ft / f_new
__device__ float d_gtA[BB*NT];        // gt / g_new
__device__ float d_hpart[576];        // hinge partials

// ---------------- FMA-only helpers (avoid MUFU bottleneck) ----------------
__device__ __forceinline__ float fexp(float x) {
    // e^x, x clamped to >= -87 (results below that are negligible in LSE sums)
    x = fmaxf(x, -87.0f);
    const float L2E_HI = 1.4426950216293335f;   // float(log2(e))
    const float L2E_LO = 1.9259630e-8f;         // log2(e) - L2E_HI
    float y = fmaf(x, L2E_HI, 12582912.0f);     // round-to-nearest-int magic (1.5*2^23)
    int   n = __float_as_int(y) - 0x4B400000;
    float fi = y - 12582912.0f;
    float r = fmaf(x, L2E_HI, -fi);
    r = fmaf(x, L2E_LO, r);                     // r in [-0.5, 0.5]
    float t = r * 0.69314718055994531f;         // r*ln2 in [-0.347, 0.347]
    float p = 1.3888889e-3f;                    // Taylor e^t degree 6
    p = fmaf(p, t, 8.3333333e-3f);
    p = fmaf(p, t, 4.1666667e-2f);
    p = fmaf(p, t, 1.6666667e-1f);
    p = fmaf(p, t, 0.5f);
    p = fmaf(p, t, 1.0f);
    p = fmaf(p, t, 1.0f);
    return p * __int_as_float((n + 127) << 23);
}

__device__ __forceinline__ float frcp(float x) {
    // bit-trick reciprocal + 3 Newton iterations (no MUFU)
    float r = __int_as_float(0x7EF311C3 - __float_as_int(x));
    r = r * fmaf(-x, r, 2.0f);
    r = r * fmaf(-x, r, 2.0f);
    r = r * fmaf(-x, r, 2.0f);
    return r;
}

// ---------------- 1) row-normalize f1, f2 ----------------
__global__ void __launch_bounds__(256) k_normalize(
    const float* __restrict__ x1, const float* __restrict__ x2,
    const float* __restrict__ x3, const float* __restrict__ x4)
{
    int row   = blockIdx.x;                 // 0 .. 2*BB*NT-1
    int which = (row >= BB*NT) ? 1 : 0;     // 0 -> f1, 1 -> f2
    int r     = which ? row - BB*NT : row;
    int b = r / NT, i = r % NT;
    const float* src;
    if (i < NR) src = (which ? x2 : x1) + ((size_t)(b*NR + i)) * DD;
    else        src = (which ? x4 : x3) + ((size_t)(b*NP + (i - NR))) * DD;
    float* dst = (which ? d_f2n : d_f1n) + (size_t)r * DD;

    int t = threadIdx.x;                    // 256 == DD
    float v = src[t];
    float sq = v * v;
    __shared__ float sh[8];
    __shared__ float s_tot;
    #pragma unroll
    for (int o = 16; o; o >>= 1) sq += __shfl_xor_sync(0xffffffffu, sq, o);
    if ((t & 31) == 0) sh[t >> 5] = sq;
    __syncthreads();
    if (t == 0) {
        float tot = 0.f;
        #pragma unroll
        for (int w = 0; w < 8; w++) tot += sh[w];
        s_tot = tot;
    }
    __syncthreads();
    float rn = 1.0f / fmaxf(sqrtf(s_tot), 1e-12f);
    dst[t] = v * rn;
}

// ---------------- 2) S[b,i,j] = exp(10 * <f1n_i, f2n_j>) (into d_C) ----------------
__global__ void __launch_bounds__(256) k_sim_gemm()
{
    int b  = blockIdx.z;
    int m0 = blockIdx.y * 64, n0 = blockIdx.x * 64;
    const float* A  = d_f1n + (size_t)b * NT * DD;
    const float* Bm = d_f2n + (size_t)b * NT * DD;
    __shared__ float As[32][65];
    __shared__ float Bs[32][65];
    int tid = threadIdx.x;
    int tx = tid & 15, ty = tid >> 4;
    float acc[4][4] = {};
    for (int k0 = 0; k0 < DD; k0 += 32) {
        #pragma unroll
        for (int h = 0; h < 2; h++) {
            int rr = (tid >> 3) + h * 32;
            int kk = (tid & 7) * 4;
            float4 av = *(const float4*)&A [(size_t)(m0 + rr) * DD + k0 + kk];
            As[kk+0][rr] = av.x; As[kk+1][rr] = av.y; As[kk+2][rr] = av.z; As[kk+3][rr] = av.w;
            float4 bv = *(const float4*)&Bm[(size_t)(n0 + rr) * DD + k0 + kk];
            Bs[kk+0][rr] = bv.x; Bs[kk+1][rr] = bv.y; Bs[kk+2][rr] = bv.z; Bs[kk+3][rr] = bv.w;
        }
        __syncthreads();
        #pragma unroll
        for (int kk = 0; kk < 32; kk++) {
            float a[4], bb[4];
            #pragma unroll
            for (int u = 0; u < 4; u++) a[u]  = As[kk][ty + 16*u];
            #pragma unroll
            for (int v = 0; v < 4; v++) bb[v] = Bs[kk][tx + 16*v];
            #pragma unroll
            for (int u = 0; u < 4; u++)
                #pragma unroll
                for (int v = 0; v < 4; v++) acc[u][v] = fmaf(a[u], bb[v], acc[u][v]);
        }
        __syncthreads();
    }
    float* S = d_C + (size_t)b * NT * NT;
    #pragma unroll
    for (int u = 0; u < 4; u++) {
        int i = m0 + ty + 16*u;
        #pragma unroll
        for (int v = 0; v < 4; v++) {
            int j = n0 + tx + 16*v;
            S[(size_t)i * NT + j] = fexp(10.0f * acc[u][v]);
        }
    }
}

// ---------------- 3) row and column sums of S ----------------
__global__ void __launch_bounds__(256) k_rowsum()
{
    int row = blockIdx.x;                    // b*NT + i
    const float* S = d_C + (size_t)row * NT;
    int t = threadIdx.x;
    float s = 0.f;
    for (int j = t; j < NT; j += 256) s += S[j];
    __shared__ float sh[8];
    #pragma unroll
    for (int o = 16; o; o >>= 1) s += __shfl_xor_sync(0xffffffffu, s, o);
    if ((t & 31) == 0) sh[t >> 5] = s;
    __syncthreads();
    if (t == 0) {
        float tot = 0.f;
        #pragma unroll
        for (int w = 0; w < 8; w++) tot += sh[w];
        d_sr[row] = tot;
    }
}

__global__ void k_colsum()
{
    // block (32,8): 32 columns, 8 row-partials each
    int b = blockIdx.y;
    int j = blockIdx.x * 32 + threadIdx.x;
    const float* S = d_C + (size_t)b * NT * NT;
    float s = 0.f;
    for (int i = threadIdx.y; i < NT; i += 8) s += S[(size_t)i * NT + j];
    __shared__ float sh[8][33];
    sh[threadIdx.y][threadIdx.x] = s;
    __syncthreads();
    if (threadIdx.y == 0) {
        float tot = 0.f;
        #pragma unroll
        for (int r = 0; r < 8; r++) tot += sh[r][threadIdx.x];
        d_sc[b * NT + j] = tot;
    }
}

// ---------------- 4) C = 1 - s/(sc+sr-s) in-place, plus write C^T ----------------
__global__ void k_cost()
{
    int b  = blockIdx.z;
    int j0 = blockIdx.x * 32, i0 = blockIdx.y * 32;
    float* S  = d_C  + (size_t)b * NT * NT;
    float* CT = d_CT + (size_t)b * NT * NT;
    __shared__ float tile[32][33];
    int tx = threadIdx.x, ty = threadIdx.y;   // (32, 8)
    int j = j0 + tx;
    float scv = d_sc[b * NT + j];
    #pragma unroll
    for (int r = 0; r < 4; r++) {
        int i = i0 + ty + 8*r;
        float s   = S[(size_t)i * NT + j];
        float den = scv + d_sr[b * NT + i] - s;
        float c   = fmaf(-s, frcp(den), 1.0f);
        S[(size_t)i * NT + j] = c;            // in-place C
        tile[ty + 8*r][tx] = c;
    }
    __syncthreads();
    #pragma unroll
    for (int r = 0; r < 4; r++) {
        int ii = j0 + ty + 8*r;               // CT row (orig col)
        int jj = i0 + tx;                     // CT col (orig row)
        CT[(size_t)ii * NT + jj] = tile[tx][ty + 8*r];
    }
}

// ---------------- 5) paired softmin: f-side over C, g-side over C^T ----------------
// out[row] = -eps * LSE_j( base_j + h[j]/eps - Crow[j]/eps ),  base_j = 0 (j<NR) / -1e5
__global__ void __launch_bounds__(256) k_softmin_pair(
    const float* __restrict__ hf,   // h for f-side (g_ab) or nullptr
    const float* __restrict__ hg,   // h for g-side (f_ba) or nullptr
    float* __restrict__ outf, float* __restrict__ outg,
    float eps, float inv_eps)
{
    int blk  = blockIdx.x;
    int side = (blk >= BB*NT) ? 1 : 0;
    int row  = side ? blk - BB*NT : blk;
    int b    = row / NT;
    const float* Cm  = side ? d_CT : d_C;
    const float* hv  = side ? hg : hf;
    float*       ov  = side ? outg : outf;
    const float* Crow = Cm + (size_t)row * NT;

    int t = threadIdx.x;
    float args[4];
    #pragma unroll
    for (int u = 0; u < 4; u++) {
        int j = t + 256*u;
        if (j < NT) {
            float h = (j < NR) ? 0.0f : -100000.0f;
            if (hv) h = fmaf(hv[b * NT + j], inv_eps, h);
            args[u] = fmaf(-Crow[j], inv_eps, h);
        } else {
            args[u] = -3.0e38f;
        }
    }
    __shared__ float sh[8];
    // max
    float m = fmaxf(fmaxf(args[0], args[1]), fmaxf(args[2], args[3]));
    #pragma unroll
    for (int o = 16; o; o >>= 1) m = fmaxf(m, __shfl_xor_sync(0xffffffffu, m, o));
    if ((t & 31) == 0) sh[t >> 5] = m;
    __syncthreads();
    if (t < 32) {
        float v = (t < 8) ? sh[t] : -3.0e38f;
        #pragma unroll
        for (int o = 4; o; o >>= 1) v = fmaxf(v, __shfl_xor_sync(0xffffffffu, v, o));
        if (t == 0) sh[0] = v;
    }
    __syncthreads();
    m = sh[0];
    __syncthreads();
    // sum of exp
    float s = fexp(args[0] - m) + fexp(args[1] - m) + fexp(args[2] - m) + fexp(args[3] - m);
    #pragma unroll
    for (int o = 16; o; o >>= 1) s += __shfl_xor_sync(0xffffffffu, s, o);
    if ((t & 31) == 0) sh[t >> 5] = s;
    __syncthreads();
    if (t == 0) {
        float tot = 0.f;
        #pragma unroll
        for (int w = 0; w < 8; w++) tot += sh[w];
        ov[row] = -eps * (m + logf(tot));
    }
}

// ---------------- 6) symmetric averaging ----------------
__global__ void k_avg()
{
    int i = blockIdx.x * 256 + threadIdx.x;
    if (i < BB*NT) {
        d_fv[i] = 0.5f * (d_fv[i] + d_ftA[i]);
        d_gv[i] = 0.5f * (d_gv[i] + d_gtA[i]);
    }
}

// ---------------- 7) hinge: sum relu(0.1 - x3 @ x4^T) ----------------
__global__ void __launch_bounds__(256) k_hinge(
    const float* __restrict__ x3, const float* __restrict__ x4)
{
    int b  = blockIdx.z;
    int m0 = blockIdx.y * 64, n0 = blockIdx.x * 64;
    const float* A  = x3 + (size_t)b * NP * DD;
    const float* Bm = x4 + (size_t)b * NP * DD;
    __shared__ float As[32][65];
    __shared__ float Bs[32][65];
    int tid = threadIdx.x;
    int tx = tid & 15, ty = tid >> 4;
    float acc[4][4] = {};
    for (int k0 = 0; k0 < DD; k0 += 32) {
        #pragma unroll
        for (int h = 0; h < 2; h++) {
            int rr = (tid >> 3) + h * 32;
            int kk = (tid & 7) * 4;
            float4 av = *(const float4*)&A [(size_t)(m0 + rr) * DD + k0 + kk];
            As[kk+0][rr] = av.x; As[kk+1][rr] = av.y; As[kk+2][rr] = av.z; As[kk+3][rr] = av.w;
            float4 bv = *(const float4*)&Bm[(size_t)(n0 + rr) * DD + k0 + kk];
            Bs[kk+0][rr] = bv.x; Bs[kk+1][rr] = bv.y; Bs[kk+2][rr] = bv.z; Bs[kk+3][rr] = bv.w;
        }
        __syncthreads();
        #pragma unroll
        for (int kk = 0; kk < 32; kk++) {
            float a[4], bb[4];
            #pragma unroll
            for (int u = 0; u < 4; u++) a[u]  = As[kk][ty + 16*u];
            #pragma unroll
            for (int v = 0; v < 4; v++) bb[v] = Bs[kk][tx + 16*v];
            #pragma unroll
            for (int u = 0; u < 4; u++)
                #pragma unroll
                for (int v = 0; v < 4; v++) acc[u][v] = fmaf(a[u], bb[v], acc[u][v]);
        }
        __syncthreads();
    }
    float loc = 0.f;
    #pragma unroll
    for (int u = 0; u < 4; u++)
        #pragma unroll
        for (int v = 0; v < 4; v++) loc += fmaxf(0.1f - acc[u][v], 0.0f);
    __shared__ float sh[8];
    #pragma unroll
    for (int o = 16; o; o >>= 1) loc += __shfl_xor_sync(0xffffffffu, loc, o);
    if ((tid & 31) == 0) sh[tid >> 5] = loc;
    __syncthreads();
    if (tid == 0) {
        float tot = 0.f;
        #pragma unroll
        for (int w = 0; w < 8; w++) tot += sh[w];
        d_hpart[blockIdx.z * 36 + blockIdx.y * 6 + blockIdx.x] = tot;
    }
}

// ---------------- 8) deterministic final reduction ----------------
__global__ void k_finalize(float* __restrict__ out)
{
    int t = threadIdx.x;  // 256
    double acc = 0.0;
    for (int idx = t; idx < BB*NR; idx += 256) {
        int b = idx >> 9;          // /512
        int i = idx & 511;
        acc += (double)d_ftA[b * NT + i] + (double)d_gtA[b * NT + i];
    }
    double h = 0.0;
    for (int idx = t; idx < 576; idx += 256) h += (double)d_hpart[idx];
    __shared__ double sa[256];
    __shared__ double sb[256];
    sa[t] = acc; sb[t] = h;
    __syncthreads();
    for (int o = 128; o; o >>= 1) {
        if (t < o) { sa[t] += sa[t + o]; sb[t] += sb[t + o]; }
        __syncthreads();
    }
    if (t == 0) {
        out[0] = (float)sb[0];                    // hinge_cost
        out[1] = (float)(sa[0] / (double)BB);     // scon_cost
    }
}

// ---------------- host ----------------
extern "C" void kernel_launch(void* const* d_in, const int* in_sizes, int n_in,
                              void* d_out, int out_size)
{
    const float* x1 = (const float*)d_in[0];
    const float* x2 = (const float*)d_in[1];
    const float* x3 = (const float*)d_in[2];
    const float* x4 = (const float*)d_in[3];
    float* out = (float*)d_out;

    float *pf, *pg, *pft, *pgt;
    cudaGetSymbolAddress((void**)&pf,  d_fv);
    cudaGetSymbolAddress((void**)&pg,  d_gv);
    cudaGetSymbolAddress((void**)&pft, d_ftA);
    cudaGetSymbolAddress((void**)&pgt, d_gtA);

    k_normalize<<<2*BB*NT, 256>>>(x1, x2, x3, x4);
    k_sim_gemm<<<dim3(NT/64, NT/64, BB), 256>>>();
    k_rowsum<<<BB*NT, 256>>>();
    k_colsum<<<dim3(NT/32, BB), dim3(32, 8)>>>();
    k_cost<<<dim3(NT/32, NT/32, BB), dim3(32, 8)>>>();
    k_hinge<<<dim3(NP/64, NP/64, BB), 256>>>(x3, x4);

    // geomloss epsilon schedule: [9] + exp(arange(2ln3, 2ln0.05, 2ln0.5)) + [0.0025]
    const float EPS[8] = {9.0f, 9.0f, 2.25f, 0.5625f, 0.140625f,
                          0.03515625f, 0.0087890625f, 0.0025f};

    // init: f_ba = softmin(eps0, C, b_log); g_ab = softmin(eps0, C^T, a_log)
    k_softmin_pair<<<2*BB*NT, 256>>>(nullptr, nullptr, pf, pg, 9.0f, 1.0f/9.0f);

    for (int k = 0; k < 8; k++) {
        float e = EPS[k], ie = 1.0f / e;
        // ft = softmin(e, C, b_log + g/e); gt = softmin(e, C^T, a_log + f/e)
        k_softmin_pair<<<2*BB*NT, 256>>>(pg, pf, pft, pgt, e, ie);
        k_avg<<<(BB*NT + 255)/256, 256>>>();
    }
    // final extrapolation at eps = 0.0025
    k_softmin_pair<<<2*BB*NT, 256>>>(pg, pf, pft, pgt, 0.0025f, 400.0f);

    k_finalize<<<1, 256>>>(out);
}

// round 3
// speedup vs baseline: 2.1565x; 2.1565x over previous
#include <cuda_runtime.h>
#include <mma.h>
#include <math.h>

using namespace nvcuda;

#define BB 16      // batch
#define NR 512     // real points
#define NP 384     // padding points
#define NT 896     // total points per side
#define DD 256     // feature dim

// ---------------- scratch ----------------
__device__ float d_f1n[BB*NT*DD];       // normalized f1
__device__ float d_f2n[BB*NT*DD];       // normalized f2
__device__ float d_S  [BB*NR*NR];       // S block then C block (in-place)
__device__ float d_CT [BB*NR*NR];       // C block transposed
__device__ float d_srp[BB*7*NT];        // row-sum partials (per 128-col tile)
__device__ float d_scp[BB*7*NT];        // col-sum partials (per 128-row tile)
__device__ float d_sr[BB*NT];
__device__ float d_sc[BB*NT];
__device__ float d_du0[BB*NR];          // dual buffers (ping-pong + final)
__device__ float d_du1[BB*NR];
__device__ float d_du2[BB*NR];
__device__ float d_du3[BB*NR];
__device__ float d_hpart[144];

// ---------------- FMA-only helpers ----------------
__device__ __forceinline__ float fexp(float x) {
    x = fmaxf(x, -87.0f);
    const float L2E_HI = 1.4426950216293335f;
    const float L2E_LO = 1.9259630e-8f;
    float y = fmaf(x, L2E_HI, 12582912.0f);
    int   n = __float_as_int(y) - 0x4B400000;
    float fi = y - 12582912.0f;
    float r = fmaf(x, L2E_HI, -fi);
    r = fmaf(x, L2E_LO, r);
    float t = r * 0.69314718055994531f;
    float p = 1.3888889e-3f;
    p = fmaf(p, t, 8.3333333e-3f);
    p = fmaf(p, t, 4.1666667e-2f);
    p = fmaf(p, t, 1.6666667e-1f);
    p = fmaf(p, t, 0.5f);
    p = fmaf(p, t, 1.0f);
    p = fmaf(p, t, 1.0f);
    return p * __int_as_float((n + 127) << 23);
}

__device__ __forceinline__ float frcp(float x) {
    float r = __int_as_float(0x7EF311C3 - __float_as_int(x));
    r = r * fmaf(-x, r, 2.0f);
    r = r * fmaf(-x, r, 2.0f);
    r = r * fmaf(-x, r, 2.0f);
    return r;
}

// ---------------- 1) row-normalize ----------------
__global__ void __launch_bounds__(256) k_normalize(
    const float* __restrict__ x1, const float* __restrict__ x2,
    const float* __restrict__ x3, const float* __restrict__ x4)
{
    int row   = blockIdx.x;
    int which = (row >= BB*NT) ? 1 : 0;
    int r     = which ? row - BB*NT : row;
    int b = r / NT, i = r % NT;
    const float* src;
    if (i < NR) src = (which ? x2 : x1) + ((size_t)(b*NR + i)) * DD;
    else        src = (which ? x4 : x3) + ((size_t)(b*NP + (i - NR))) * DD;
    float* dst = (which ? d_f2n : d_f1n) + (size_t)r * DD;

    int t = threadIdx.x;
    float v = src[t];
    float sq = v * v;
    __shared__ float sh[8];
    __shared__ float s_tot;
    #pragma unroll
    for (int o = 16; o; o >>= 1) sq += __shfl_xor_sync(0xffffffffu, sq, o);
    if ((t & 31) == 0) sh[t >> 5] = sq;
    __syncthreads();
    if (t == 0) {
        float tot = 0.f;
        #pragma unroll
        for (int w = 0; w < 8; w++) tot += sh[w];
        s_tot = tot;
    }
    __syncthreads();
    float rn = 1.0f / fmaxf(sqrtf(s_tot), 1e-12f);
    dst[t] = v * rn;
}

// ---------------- 2) tf32 GEMM + exp + partial sums + S-block store ----------------
// grid (7,7,16), 256 threads (8 warps: 2 m-warps x 4 n-warps, warp tile 64x32)
#define LDA 40
#define LDE 136
__global__ void __launch_bounds__(256) k_simgemm()
{
    __shared__ float sh[10240];     // As[128*40] | Bs[128*40]; epilogue reuses as Ssh[64*136]
    __shared__ float colacc[128];
    __shared__ float warp_col[128]; // not used; kept minimal
    (void)warp_col;

    int b  = blockIdx.z;
    int m0 = blockIdx.y * 128, n0 = blockIdx.x * 128;
    const float* Ag = d_f1n + (size_t)b * NT * DD + (size_t)m0 * DD;
    const float* Bg = d_f2n + (size_t)b * NT * DD + (size_t)n0 * DD;
    float* As = sh;
    float* Bs = sh + 5120;

    int tid = threadIdx.x;
    int wid = tid >> 5;
    int warp_m = wid >> 2;          // 0..1
    int warp_n = wid & 3;           // 0..3

    wmma::fragment<wmma::accumulator,16,16,8,float> acc[4][2];
    #pragma unroll
    for (int mt = 0; mt < 4; mt++)
        #pragma unroll
        for (int nt = 0; nt < 2; nt++)
            wmma::fill_fragment(acc[mt][nt], 0.0f);

    for (int k0 = 0; k0 < DD; k0 += 32) {
        #pragma unroll
        for (int u = 0; u < 4; u++) {
            int idx = tid + 256*u;
            int row = idx >> 3;
            int c4  = (idx & 7) * 4;
            float4 va = *(const float4*)(Ag + (size_t)row*DD + k0 + c4);
            As[row*LDA + c4 + 0] = wmma::__float_to_tf32(va.x);
            As[row*LDA + c4 + 1] = wmma::__float_to_tf32(va.y);
            As[row*LDA + c4 + 2] = wmma::__float_to_tf32(va.z);
            As[row*LDA + c4 + 3] = wmma::__float_to_tf32(va.w);
            float4 vb = *(const float4*)(Bg + (size_t)row*DD + k0 + c4);
            Bs[row*LDA + c4 + 0] = wmma::__float_to_tf32(vb.x);
            Bs[row*LDA + c4 + 1] = wmma::__float_to_tf32(vb.y);
            Bs[row*LDA + c4 + 2] = wmma::__float_to_tf32(vb.z);
            Bs[row*LDA + c4 + 3] = wmma::__float_to_tf32(vb.w);
        }
        __syncthreads();
        #pragma unroll
        for (int ks = 0; ks < 4; ks++) {
            wmma::fragment<wmma::matrix_b,16,16,8,wmma::precision::tf32,wmma::col_major> bf[2];
            #pragma unroll
            for (int nt = 0; nt < 2; nt++)
                wmma::load_matrix_sync(bf[nt], &Bs[(warp_n*32 + nt*16)*LDA + ks*8], LDA);
            #pragma unroll
            for (int mt = 0; mt < 4; mt++) {
                wmma::fragment<wmma::matrix_a,16,16,8,wmma::precision::tf32,wmma::row_major> af;
                wmma::load_matrix_sync(af, &As[(warp_m*64 + mt*16)*LDA + ks*8], LDA);
                #pragma unroll
                for (int nt = 0; nt < 2; nt++)
                    wmma::mma_sync(acc[mt][nt], af, bf[nt], acc[mt][nt]);
            }
        }
        __syncthreads();
    }

    if (tid < 128) colacc[tid] = 0.f;
    __syncthreads();

    bool inblk = (m0 < NR) && (n0 < NR);
    int r   = tid >> 2;     // 0..63 local row
    int seg = tid & 3;      // 32-col segment

    #pragma unroll
    for (int phase = 0; phase < 2; phase++) {
        if (warp_m == phase) {
            #pragma unroll
            for (int mt = 0; mt < 4; mt++)
                #pragma unroll
                for (int nt = 0; nt < 2; nt++)
                    wmma::store_matrix_sync(&sh[(mt*16)*LDE + warp_n*32 + nt*16],
                                            acc[mt][nt], LDE, wmma::mem_row_major);
        }
        __syncthreads();

        int ig = m0 + phase*64 + r;            // global row
        float rsum = 0.f;
        float* Srow = d_S + ((size_t)b*NR + ig)*NR + n0 + seg*32;
        #pragma unroll
        for (int q = 0; q < 8; q++) {
            float4 v4 = *(float4*)&sh[r*LDE + seg*32 + q*4];
            v4.x = fexp(10.0f * v4.x);
            v4.y = fexp(10.0f * v4.y);
            v4.z = fexp(10.0f * v4.z);
            v4.w = fexp(10.0f * v4.w);
            rsum += (v4.x + v4.y) + (v4.z + v4.w);
            *(float4*)&sh[r*LDE + seg*32 + q*4] = v4;
            if (inblk) *(float4*)(Srow + q*4) = v4;
        }
        rsum += __shfl_down_sync(0xffffffffu, rsum, 2);
        rsum += __shfl_down_sync(0xffffffffu, rsum, 1);
        if (seg == 0) d_srp[((size_t)b*7 + (n0 >> 7))*NT + ig] = rsum;
        __syncthreads();

        // column partial sums over these 64 rows
        int col  = tid >> 1;     // 0..127
        int half = tid & 1;      // 32-row half
        float cs = 0.f;
        #pragma unroll
        for (int rr = 0; rr < 32; rr++)
            cs += sh[(half*32 + rr)*LDE + col];
        cs += __shfl_down_sync(0xffffffffu, cs, 1);
        if (half == 0) colacc[col] += cs;
        __syncthreads();
    }
    if (tid < 128) d_scp[((size_t)b*7 + (m0 >> 7))*NT + n0 + tid] = colacc[tid];
}

// ---------------- 3) reduce partial sums ----------------
__global__ void k_sums()
{
    int idx = blockIdx.x * 256 + threadIdx.x;   // 2*BB*NT total
    if (idx >= 2*BB*NT) return;
    int which = idx >= BB*NT;
    int r = which ? idx - BB*NT : idx;
    int b = r / NT, i = r % NT;
    const float* P = (which ? d_scp : d_srp) + (size_t)b*7*NT + i;
    float s = 0.f;
    #pragma unroll
    for (int t = 0; t < 7; t++) s += P[(size_t)t*NT];
    (which ? d_sc : d_sr)[r] = s;
}

// ---------------- 4) cost on 512-block: C = 1 - s/(sc+sr-s), plus C^T ----------------
__global__ void k_cost()
{
    int b  = blockIdx.z;
    int j0 = blockIdx.x * 32, i0 = blockIdx.y * 32;
    float* S  = d_S  + (size_t)b * NR * NR;
    float* CT = d_CT + (size_t)b * NR * NR;
    __shared__ float tile[32][33];
    int tx = threadIdx.x, ty = threadIdx.y;   // (32, 8)
    int j = j0 + tx;
    float scv = d_sc[b * NT + j];
    #pragma unroll
    for (int r = 0; r < 4; r++) {
        int i = i0 + ty + 8*r;
        float s   = S[(size_t)i * NR + j];
        float den = scv + d_sr[b * NT + i] - s;
        float c   = fmaf(-s, frcp(den), 1.0f);
        S[(size_t)i * NR + j] = c;
        tile[ty + 8*r][tx] = c;
    }
    __syncthreads();
    #pragma unroll
    for (int r = 0; r < 4; r++) {
        int ii = j0 + ty + 8*r;
        int jj = i0 + tx;
        CT[(size_t)ii * NR + jj] = tile[tx][ty + 8*r];
    }
}

// ---------------- 5) paired softmin over 512-block, with fused averaging ----------------
__global__ void __launch_bounds__(256) k_softmin_pair(
    const float* __restrict__ hf, const float* __restrict__ hg,
    const float* __restrict__ oldf, const float* __restrict__ oldg,
    float* __restrict__ outf, float* __restrict__ outg,
    float eps, float inv_eps, int avg)
{
    int blk  = blockIdx.x;
    int side = (blk >= BB*NR) ? 1 : 0;
    int row  = side ? blk - BB*NR : blk;
    int b    = row >> 9;
    const float* Crow = (side ? d_CT : d_S) + (size_t)row * NR;
    const float* hv   = side ? hg : hf;
    const float* oldv = side ? oldg : oldf;
    float*       ov   = side ? outg : outf;

    int t = threadIdx.x;
    float a0, a1;
    {
        float h0 = hv ? hv[(b<<9) + t]       * inv_eps : 0.0f;
        float h1 = hv ? hv[(b<<9) + t + 256] * inv_eps : 0.0f;
        a0 = fmaf(-Crow[t],       inv_eps, h0);
        a1 = fmaf(-Crow[t + 256], inv_eps, h1);
    }
    __shared__ float sh[8];
    float m = fmaxf(a0, a1);
    #pragma unroll
    for (int o = 16; o; o >>= 1) m = fmaxf(m, __shfl_xor_sync(0xffffffffu, m, o));
    if ((t & 31) == 0) sh[t >> 5] = m;
    __syncthreads();
    if (t < 32) {
        float v = (t < 8) ? sh[t] : -3.0e38f;
        #pragma unroll
        for (int o = 4; o; o >>= 1) v = fmaxf(v, __shfl_xor_sync(0xffffffffu, v, o));
        if (t == 0) sh[0] = v;
    }
    __syncthreads();
    m = sh[0];
    __syncthreads();
    float s = fexp(a0 - m) + fexp(a1 - m);
    #pragma unroll
    for (int o = 16; o; o >>= 1) s += __shfl_xor_sync(0xffffffffu, s, o);
    if ((t & 31) == 0) sh[t >> 5] = s;
    __syncthreads();
    if (t == 0) {
        float tot = 0.f;
        #pragma unroll
        for (int w = 0; w < 8; w++) tot += sh[w];
        float val = -eps * (m + logf(tot));
        if (avg) val = 0.5f * (oldv[row] + val);
        ov[row] = val;
    }
}

// ---------------- 6) hinge GEMM (tf32), block-local reduction ----------------
__global__ void __launch_bounds__(256) k_hinge(
    const float* __restrict__ x3, const float* __restrict__ x4)
{
    __shared__ float sh[10240];
    int b  = blockIdx.z;
    int m0 = blockIdx.y * 128, n0 = blockIdx.x * 128;
    const float* Ag = x3 + (size_t)b * NP * DD + (size_t)m0 * DD;
    const float* Bg = x4 + (size_t)b * NP * DD + (size_t)n0 * DD;
    float* As = sh;
    float* Bs = sh + 5120;

    int tid = threadIdx.x;
    int wid = tid >> 5;
    int warp_m = wid >> 2;
    int warp_n = wid & 3;

    wmma::fragment<wmma::accumulator,16,16,8,float> acc[4][2];
    #pragma unroll
    for (int mt = 0; mt < 4; mt++)
        #pragma unroll
        for (int nt = 0; nt < 2; nt++)
            wmma::fill_fragment(acc[mt][nt], 0.0f);

    for (int k0 = 0; k0 < DD; k0 += 32) {
        #pragma unroll
        for (int u = 0; u < 4; u++) {
            int idx = tid + 256*u;
            int row = idx >> 3;
            int c4  = (idx & 7) * 4;
            float4 va = *(const float4*)(Ag + (size_t)row*DD + k0 + c4);
            As[row*LDA + c4 + 0] = wmma::__float_to_tf32(va.x);
            As[row*LDA + c4 + 1] = wmma::__float_to_tf32(va.y);
            As[row*LDA + c4 + 2] = wmma::__float_to_tf32(va.z);
            As[row*LDA + c4 + 3] = wmma::__float_to_tf32(va.w);
            float4 vb = *(const float4*)(Bg + (size_t)row*DD + k0 + c4);
            Bs[row*LDA + c4 + 0] = wmma::__float_to_tf32(vb.x);
            Bs[row*LDA + c4 + 1] = wmma::__float_to_tf32(vb.y);
            Bs[row*LDA + c4 + 2] = wmma::__float_to_tf32(vb.z);
            Bs[row*LDA + c4 + 3] = wmma::__float_to_tf32(vb.w);
        }
        __syncthreads();
        #pragma unroll
        for (int ks = 0; ks < 4; ks++) {
            wmma::fragment<wmma::matrix_b,16,16,8,wmma::precision::tf32,wmma::col_major> bf[2];
            #pragma unroll
            for (int nt = 0; nt < 2; nt++)
                wmma::load_matrix_sync(bf[nt], &Bs[(warp_n*32 + nt*16)*LDA + ks*8], LDA);
            #pragma unroll
            for (int mt = 0; mt < 4; mt++) {
                wmma::fragment<wmma::matrix_a,16,16,8,wmma::precision::tf32,wmma::row_major> af;
                wmma::load_matrix_sync(af, &As[(warp_m*64 + mt*16)*LDA + ks*8], LDA);
                #pragma unroll
                for (int nt = 0; nt < 2; nt++)
                    wmma::mma_sync(acc[mt][nt], af, bf[nt], acc[mt][nt]);
            }
        }
        __syncthreads();
    }

    // relu(0.1 - v) sum: layout-independent over fragment elements
    float loc = 0.f;
    #pragma unroll
    for (int mt = 0; mt < 4; mt++)
        #pragma unroll
        for (int nt = 0; nt < 2; nt++)
            #pragma unroll
            for (int e = 0; e < acc[mt][nt].num_elements; e++)
                loc += fmaxf(0.1f - acc[mt][nt].x[e], 0.0f);

    __shared__ float red[8];
    #pragma unroll
    for (int o = 16; o; o >>= 1) loc += __shfl_xor_sync(0xffffffffu, loc, o);
    if ((tid & 31) == 0) red[tid >> 5] = loc;
    __syncthreads();
    if (tid == 0) {
        float tot = 0.f;
        #pragma unroll
        for (int w = 0; w < 8; w++) tot += red[w];
        d_hpart[blockIdx.z * 9 + blockIdx.y * 3 + blockIdx.x] = tot;
    }
}

// ---------------- 7) deterministic final reduction ----------------
__global__ void k_finalize(float* __restrict__ out)
{
    int t = threadIdx.x;  // 256
    double acc = 0.0;
    for (int idx = t; idx < BB*NR; idx += 256)
        acc += (double)d_du2[idx] + (double)d_du3[idx];
    double h = 0.0;
    for (int idx = t; idx < 144; idx += 256) h += (double)d_hpart[idx];
    __shared__ double sa[256];
    __shared__ double sb[256];
    sa[t] = acc; sb[t] = h;
    __syncthreads();
    for (int o = 128; o; o >>= 1) {
        if (t < o) { sa[t] += sa[t + o]; sb[t] += sb[t + o]; }
        __syncthreads();
    }
    if (t == 0) {
        out[0] = (float)sb[0];
        out[1] = (float)(sa[0] / (double)BB);
    }
}

// ---------------- host ----------------
extern "C" void kernel_launch(void* const* d_in, const int* in_sizes, int n_in,
                              void* d_out, int out_size)
{
    const float* x1 = (const float*)d_in[0];
    const float* x2 = (const float*)d_in[1];
    const float* x3 = (const float*)d_in[2];
    const float* x4 = (const float*)d_in[3];
    float* out = (float*)d_out;

    float *p0, *p1, *p2, *p3;
    cudaGetSymbolAddress((void**)&p0, d_du0);
    cudaGetSymbolAddress((void**)&p1, d_du1);
    cudaGetSymbolAddress((void**)&p2, d_du2);
    cudaGetSymbolAddress((void**)&p3, d_du3);

    k_normalize<<<2*BB*NT, 256>>>(x1, x2, x3, x4);
    k_simgemm<<<dim3(7, 7, BB), 256>>>();
    k_sums<<<(2*BB*NT + 255)/256, 256>>>();
    k_cost<<<dim3(NR/32, NR/32, BB), dim3(32, 8)>>>();
    k_hinge<<<dim3(3, 3, BB), 256>>>(x3, x4);

    const float EPS[8] = {9.0f, 9.0f, 2.25f, 0.5625f, 0.140625f,
                          0.03515625f, 0.0087890625f, 0.0025f};

    // init: f = softmin(eps0, C, b_log); g = softmin(eps0, C^T, a_log)  (h = 0)
    k_softmin_pair<<<2*BB*NR, 256>>>(nullptr, nullptr, nullptr, nullptr,
                                     p0, p1, 9.0f, 1.0f/9.0f, 0);

    float *fc = p0, *gc = p1, *fa = p2, *ga = p3;
    for (int k = 0; k < 8; k++) {
        float e = EPS[k], ie = 1.0f / e;
        // ft = softmin(C, g/e) -> 0.5(f+ft); gt = softmin(C^T, f/e) -> 0.5(g+gt)
        k_softmin_pair<<<2*BB*NR, 256>>>(gc, fc, fc, gc, fa, ga, e, ie, 1);
        float* tf = fc; fc = fa; fa = tf;
        float* tg = gc; gc = ga; ga = tg;
    }
    // final extrapolation at eps = 0.0025 into d_du2/d_du3
    k_softmin_pair<<<2*BB*NR, 256>>>(gc, fc, nullptr, nullptr, p2, p3,
                                     0.0025f, 400.0f, 0);

    k_finalize<<<1, 256>>>(out);
}

// round 5
// speedup vs baseline: 2.1666x; 1.0047x over previous
#include <cuda_runtime.h>
#include <cstdint>
#include <mma.h>
#include <math.h>

using namespace nvcuda;

#define BB 16      // batch
#define NR 512     // real points
#define NP 384     // padding points
#define NT 896     // total points per side
#define DD 256     // feature dim

// ---------------- scratch ----------------
__device__ float d_f1n[BB*NT*DD];
__device__ float d_f2n[BB*NT*DD];
__device__ float d_S  [BB*NR*NR];       // S then C (in-place)
__device__ float d_CT [BB*NR*NR];       // C transposed
__device__ float d_srp[BB*7*NT];
__device__ float d_scp[BB*7*NT];
__device__ float d_sr[BB*NT];
__device__ float d_sc[BB*NT];
__device__ float d_du0[BB*NR];
__device__ float d_du1[BB*NR];
__device__ float d_du2[BB*NR];
__device__ float d_du3[BB*NR];
__device__ float d_hpart[144];

// ---------------- FMA-only helpers ----------------
__device__ __forceinline__ float fexp(float x) {
    x = fmaxf(x, -87.0f);
    const float L2E_HI = 1.4426950216293335f;
    const float L2E_LO = 1.9259630e-8f;
    float y = fmaf(x, L2E_HI, 12582912.0f);
    int   n = __float_as_int(y) - 0x4B400000;
    float fi = y - 12582912.0f;
    float r = fmaf(x, L2E_HI, -fi);
    r = fmaf(x, L2E_LO, r);
    float t = r * 0.69314718055994531f;
    float p = 1.3888889e-3f;
    p = fmaf(p, t, 8.3333333e-3f);
    p = fmaf(p, t, 4.1666667e-2f);
    p = fmaf(p, t, 1.6666667e-1f);
    p = fmaf(p, t, 0.5f);
    p = fmaf(p, t, 1.0f);
    p = fmaf(p, t, 1.0f);
    return p * __int_as_float((n + 127) << 23);
}

__device__ __forceinline__ float frcp(float x) {
    float r = __int_as_float(0x7EF311C3 - __float_as_int(x));
    r = r * fmaf(-x, r, 2.0f);
    r = r * fmaf(-x, r, 2.0f);
    r = r * fmaf(-x, r, 2.0f);
    return r;
}

__device__ __forceinline__ void cp16(void* s, const void* g) {
    unsigned int sa = (unsigned int)__cvta_generic_to_shared(s);
    asm volatile("cp.async.cg.shared.global [%0], [%1], 16;" :: "r"(sa), "l"(g));
}

// ---------------- 1) row-normalize (warp per row) ----------------
__global__ void __launch_bounds__(256) k_normalize(
    const float* __restrict__ x1, const float* __restrict__ x2,
    const float* __restrict__ x3, const float* __restrict__ x4)
{
    int gw   = blockIdx.x * 8 + (threadIdx.x >> 5);
    int lane = threadIdx.x & 31;
    int which = (gw >= BB*NT) ? 1 : 0;
    int r     = which ? gw - BB*NT : gw;
    int b = r / NT, i = r % NT;
    const float* src;
    if (i < NR) src = (which ? x2 : x1) + ((size_t)(b*NR + i)) * DD;
    else        src = (which ? x4 : x3) + ((size_t)(b*NP + (i - NR))) * DD;
    float* dst = (which ? d_f2n : d_f1n) + (size_t)r * DD;

    float4 v0 = *(const float4*)(src + lane*4);
    float4 v1 = *(const float4*)(src + 128 + lane*4);
    float sq = v0.x*v0.x + v0.y*v0.y + v0.z*v0.z + v0.w*v0.w
             + v1.x*v1.x + v1.y*v1.y + v1.z*v1.z + v1.w*v1.w;
    #pragma unroll
    for (int o = 16; o; o >>= 1) sq += __shfl_xor_sync(0xffffffffu, sq, o);
    float rn = 1.0f / fmaxf(sqrtf(sq), 1e-12f);
    v0.x *= rn; v0.y *= rn; v0.z *= rn; v0.w *= rn;
    v1.x *= rn; v1.y *= rn; v1.z *= rn; v1.w *= rn;
    *(float4*)(dst + lane*4)       = v0;
    *(float4*)(dst + 128 + lane*4) = v1;
}

// ---------------- 2) pipelined tf32 GEMM + exp + partial sums ----------------
#define LDA 40
#define LDE 136
#define STAGE (128*LDA)       // 5120 floats
#define SIM_SMEM (4*STAGE*4)  // 81920 bytes

__global__ void __launch_bounds__(256) k_simgemm()
{
    extern __shared__ float sh[];   // 2 stages x (As | Bs); epilogue reuse
    __shared__ float colacc[128];

    int b  = blockIdx.z;
    int m0 = blockIdx.y * 128, n0 = blockIdx.x * 128;
    const float* Ag = d_f1n + (size_t)b * NT * DD + (size_t)m0 * DD;
    const float* Bg = d_f2n + (size_t)b * NT * DD + (size_t)n0 * DD;

    int tid = threadIdx.x;
    int wid = tid >> 5;
    int warp_m = wid >> 2;
    int warp_n = wid & 3;

    wmma::fragment<wmma::accumulator,16,16,8,float> acc[4][2];
    #pragma unroll
    for (int mt = 0; mt < 4; mt++)
        #pragma unroll
        for (int nt = 0; nt < 2; nt++)
            wmma::fill_fragment(acc[mt][nt], 0.0f);

    int lrow = tid >> 3;
    int lc4  = (tid & 7) * 4;

    {
        float* A = sh; float* B = sh + STAGE;
        #pragma unroll
        for (int u = 0; u < 4; u++) {
            int row = lrow + 32*u;
            cp16(&A[row*LDA + lc4], Ag + (size_t)row*DD + lc4);
            cp16(&B[row*LDA + lc4], Bg + (size_t)row*DD + lc4);
        }
        asm volatile("cp.async.commit_group;");
    }

    for (int kc = 0; kc < 8; kc++) {
        if (kc < 7) {
            float* A = sh + ((kc+1)&1)*2*STAGE;
            float* B = A + STAGE;
            int k0 = (kc+1)*32;
            #pragma unroll
            for (int u = 0; u < 4; u++) {
                int row = lrow + 32*u;
                cp16(&A[row*LDA + lc4], Ag + (size_t)row*DD + k0 + lc4);
                cp16(&B[row*LDA + lc4], Bg + (size_t)row*DD + k0 + lc4);
            }
            asm volatile("cp.async.commit_group;");
            asm volatile("cp.async.wait_group 1;");
        } else {
            asm volatile("cp.async.wait_group 0;");
        }
        __syncthreads();
        const float* A = sh + (kc&1)*2*STAGE;
        const float* B = A + STAGE;
        #pragma unroll
        for (int ks = 0; ks < 4; ks++) {
            wmma::fragment<wmma::matrix_b,16,16,8,wmma::precision::tf32,wmma::col_major> bf[2];
            #pragma unroll
            for (int nt = 0; nt < 2; nt++)
                wmma::load_matrix_sync(bf[nt], &B[(warp_n*32 + nt*16)*LDA + ks*8], LDA);
            #pragma unroll
            for (int mt = 0; mt < 4; mt++) {
                wmma::fragment<wmma::matrix_a,16,16,8,wmma::precision::tf32,wmma::row_major> af;
                wmma::load_matrix_sync(af, &A[(warp_m*64 + mt*16)*LDA + ks*8], LDA);
                #pragma unroll
                for (int nt = 0; nt < 2; nt++)
                    wmma::mma_sync(acc[mt][nt], af, bf[nt], acc[mt][nt]);
            }
        }
        __syncthreads();
    }

    if (tid < 128) colacc[tid] = 0.f;
    __syncthreads();

    bool inblk = (m0 < NR) && (n0 < NR);
    int r   = tid >> 2;
    int seg = tid & 3;

    #pragma unroll
    for (int phase = 0; phase < 2; phase++) {
        if (warp_m == phase) {
            #pragma unroll
            for (int mt = 0; mt < 4; mt++)
                #pragma unroll
                for (int nt = 0; nt < 2; nt++)
                    wmma::store_matrix_sync(&sh[(mt*16)*LDE + warp_n*32 + nt*16],
                                            acc[mt][nt], LDE, wmma::mem_row_major);
        }
        __syncthreads();

        int ig = m0 + phase*64 + r;
        float rsum = 0.f;
        float* Srow = d_S + ((size_t)b*NR + ig)*NR + n0 + seg*32;
        #pragma unroll
        for (int q = 0; q < 8; q++) {
            float4 v4 = *(float4*)&sh[r*LDE + seg*32 + q*4];
            v4.x = fexp(10.0f * v4.x);
            v4.y = fexp(10.0f * v4.y);
            v4.z = fexp(10.0f * v4.z);
            v4.w = fexp(10.0f * v4.w);
            rsum += (v4.x + v4.y) + (v4.z + v4.w);
            *(float4*)&sh[r*LDE + seg*32 + q*4] = v4;
            if (inblk) *(float4*)(Srow + q*4) = v4;
        }
        rsum += __shfl_down_sync(0xffffffffu, rsum, 2);
        rsum += __shfl_down_sync(0xffffffffu, rsum, 1);
        if (seg == 0) d_srp[((size_t)b*7 + (n0 >> 7))*NT + ig] = rsum;
        __syncthreads();

        int col  = tid >> 1;
        int half = tid & 1;
        float cs = 0.f;
        #pragma unroll
        for (int rr = 0; rr < 32; rr++)
            cs += sh[(half*32 + rr)*LDE + col];
        cs += __shfl_down_sync(0xffffffffu, cs, 1);
        if (half == 0) colacc[col] += cs;
        __syncthreads();
    }
    if (tid < 128) d_scp[((size_t)b*7 + (m0 >> 7))*NT + n0 + tid] = colacc[tid];
}

// ---------------- 3) reduce partial sums ----------------
__global__ void k_sums()
{
    int idx = blockIdx.x * 256 + threadIdx.x;
    if (idx >= 2*BB*NT) return;
    int which = idx >= BB*NT;
    int r = which ? idx - BB*NT : idx;
    int b = r / NT, i = r % NT;
    const float* P = (which ? d_scp : d_srp) + (size_t)b*7*NT + i;
    float s = 0.f;
    #pragma unroll
    for (int t = 0; t < 7; t++) s += P[(size_t)t*NT];
    (which ? d_sc : d_sr)[r] = s;
}

// ---------------- 4) cost: C = 1 - s/(sc+sr-s) in-place + C^T (float4) ----------------
__global__ void __launch_bounds__(256) k_cost()
{
    __shared__ float tile[64][68];
    int b  = blockIdx.z;
    int j0 = blockIdx.x * 64, i0 = blockIdx.y * 64;
    float* S  = d_S  + (size_t)b * NR * NR;
    float* CT = d_CT + (size_t)b * NR * NR;
    int tx = threadIdx.x & 15, ty = threadIdx.x >> 4;
    int j = j0 + tx*4;
    float4 sc4 = *(const float4*)(d_sc + b*NT + j);
    #pragma unroll
    for (int rr = 0; rr < 4; rr++) {
        int i = i0 + ty + 16*rr;
        float sr = d_sr[b*NT + i];
        float4 s4 = *(float4*)(S + (size_t)i*NR + j);
        float4 c4;
        c4.x = fmaf(-s4.x, frcp(sc4.x + sr - s4.x), 1.0f);
        c4.y = fmaf(-s4.y, frcp(sc4.y + sr - s4.y), 1.0f);
        c4.z = fmaf(-s4.z, frcp(sc4.z + sr - s4.z), 1.0f);
        c4.w = fmaf(-s4.w, frcp(sc4.w + sr - s4.w), 1.0f);
        *(float4*)(S + (size_t)i*NR + j) = c4;
        int il = ty + 16*rr;
        tile[tx*4+0][il] = c4.x;
        tile[tx*4+1][il] = c4.y;
        tile[tx*4+2][il] = c4.z;
        tile[tx*4+3][il] = c4.w;
    }
    __syncthreads();
    #pragma unroll
    for (int rr = 0; rr < 4; rr++) {
        int jl = ty + 16*rr;
        float4 o;
        o.x = tile[jl][tx*4+0];
        o.y = tile[jl][tx*4+1];
        o.z = tile[jl][tx*4+2];
        o.w = tile[jl][tx*4+3];
        *(float4*)(CT + (size_t)(j0+jl)*NR + i0 + tx*4) = o;
    }
}

// ---------------- 5) softmin: warp per row, shfl-only reductions ----------------
__global__ void __launch_bounds__(256) k_softmin_pair(
    const float* __restrict__ hf, const float* __restrict__ hg,
    const float* __restrict__ oldf, const float* __restrict__ oldg,
    float* __restrict__ outf, float* __restrict__ outg,
    float eps, float inv_eps, int avg)
{
    int gw   = blockIdx.x * 8 + (threadIdx.x >> 5);
    int lane = threadIdx.x & 31;
    int side = (gw >= BB*NR) ? 1 : 0;
    int row  = side ? gw - BB*NR : gw;
    int b    = row >> 9;
    const float* Crow = (side ? d_CT : d_S) + (size_t)row * NR;
    const float* hv   = side ? hg : hf;
    const float* oldv = side ? oldg : oldf;
    float*       ov   = side ? outg : outf;
    const float* hb   = hv ? hv + (b << 9) : nullptr;

    float a[16];
    #pragma unroll
    for (int q = 0; q < 4; q++) {
        int j = q*128 + lane*4;
        float4 c4 = *(const float4*)(Crow + j);
        if (hb) {
            float4 h4 = *(const float4*)(hb + j);
            a[q*4+0] = (h4.x - c4.x) * inv_eps;
            a[q*4+1] = (h4.y - c4.y) * inv_eps;
            a[q*4+2] = (h4.z - c4.z) * inv_eps;
            a[q*4+3] = (h4.w - c4.w) * inv_eps;
        } else {
            a[q*4+0] = -c4.x * inv_eps;
            a[q*4+1] = -c4.y * inv_eps;
            a[q*4+2] = -c4.z * inv_eps;
            a[q*4+3] = -c4.w * inv_eps;
        }
    }
    float m = a[0];
    #pragma unroll
    for (int u = 1; u < 16; u++) m = fmaxf(m, a[u]);
    #pragma unroll
    for (int o = 16; o; o >>= 1) m = fmaxf(m, __shfl_xor_sync(0xffffffffu, m, o));
    float s = 0.f;
    #pragma unroll
    for (int u = 0; u < 16; u++) s += fexp(a[u] - m);
    #pragma unroll
    for (int o = 16; o; o >>= 1) s += __shfl_xor_sync(0xffffffffu, s, o);
    if (lane == 0) {
        float val = -eps * (m + logf(s));
        if (avg) val = 0.5f * (oldv[row] + val);
        ov[row] = val;
    }
}

// ---------------- 6) hinge GEMM (pipelined tf32) ----------------
__global__ void __launch_bounds__(256) k_hinge(
    const float* __restrict__ x3, const float* __restrict__ x4)
{
    extern __shared__ float sh[];
    int b  = blockIdx.z;
    int m0 = blockIdx.y * 128, n0 = blockIdx.x * 128;
    const float* Ag = x3 + (size_t)b * NP * DD + (size_t)m0 * DD;
    const float* Bg = x4 + (size_t)b * NP * DD + (size_t)n0 * DD;

    int tid = threadIdx.x;
    int wid = tid >> 5;
    int warp_m = wid >> 2;
    int warp_n = wid & 3;

    wmma::fragment<wmma::accumulator,16,16,8,float> acc[4][2];
    #pragma unroll
    for (int mt = 0; mt < 4; mt++)
        #pragma unroll
        for (int nt = 0; nt < 2; nt++)
            wmma::fill_fragment(acc[mt][nt], 0.0f);

    int lrow = tid >> 3;
    int lc4  = (tid & 7) * 4;

    {
        float* A = sh; float* B = sh + STAGE;
        #pragma unroll
        for (int u = 0; u < 4; u++) {
            int row = lrow + 32*u;
            cp16(&A[row*LDA + lc4], Ag + (size_t)row*DD + lc4);
            cp16(&B[row*LDA + lc4], Bg + (size_t)row*DD + lc4);
        }
        asm volatile("cp.async.commit_group;");
    }

    for (int kc = 0; kc < 8; kc++) {
        if (kc < 7) {
            float* A = sh + ((kc+1)&1)*2*STAGE;
            float* B = A + STAGE;
            int k0 = (kc+1)*32;
            #pragma unroll
            for (int u = 0; u < 4; u++) {
                int row = lrow + 32*u;
                cp16(&A[row*LDA + lc4], Ag + (size_t)row*DD + k0 + lc4);
                cp16(&B[row*LDA + lc4], Bg + (size_t)row*DD + k0 + lc4);
            }
            asm volatile("cp.async.commit_group;");
            asm volatile("cp.async.wait_group 1;");
        } else {
            asm volatile("cp.async.wait_group 0;");
        }
        __syncthreads();
        const float* A = sh + (kc&1)*2*STAGE;
        const float* B = A + STAGE;
        #pragma unroll
        for (int ks = 0; ks < 4; ks++) {
            wmma::fragment<wmma::matrix_b,16,16,8,wmma::precision::tf32,wmma::col_major> bf[2];
            #pragma unroll
            for (int nt = 0; nt < 2; nt++)
                wmma::load_matrix_sync(bf[nt], &B[(warp_n*32 + nt*16)*LDA + ks*8], LDA);
            #pragma unroll
            for (int mt = 0; mt < 4; mt++) {
                wmma::fragment<wmma::matrix_a,16,16,8,wmma::precision::tf32,wmma::row_major> af;
                wmma::load_matrix_sync(af, &A[(warp_m*64 + mt*16)*LDA + ks*8], LDA);
                #pragma unroll
                for (int nt = 0; nt < 2; nt++)
                    wmma::mma_sync(acc[mt][nt], af, bf[nt], acc[mt][nt]);
            }
        }
        __syncthreads();
    }

    float loc = 0.f;
    #pragma unroll
    for (int mt = 0; mt < 4; mt++)
        #pragma unroll
        for (int nt = 0; nt < 2; nt++)
            #pragma unroll
            for (int e = 0; e < acc[mt][nt].num_elements; e++)
                loc += fmaxf(0.1f - acc[mt][nt].x[e], 0.0f);

    __shared__ float red[8];
    #pragma unroll
    for (int o = 16; o; o >>= 1) loc += __shfl_xor_sync(0xffffffffu, loc, o);
    if ((tid & 31) == 0) red[tid >> 5] = loc;
    __syncthreads();
    if (tid == 0) {
        float tot = 0.f;
        #pragma unroll
        for (int w = 0; w < 8; w++) tot += red[w];
        d_hpart[blockIdx.z * 9 + blockIdx.y * 3 + blockIdx.x] = tot;
    }
}

// ---------------- 7) deterministic final reduction ----------------
__global__ void k_finalize(float* __restrict__ out)
{
    int t = threadIdx.x;
    double acc = 0.0;
    for (int idx = t; idx < BB*NR; idx += 256)
        acc += (double)d_du2[idx] + (double)d_du3[idx];
    double h = 0.0;
    for (int idx = t; idx < 144; idx += 256) h += (double)d_hpart[idx];
    __shared__ double sa[256];
    __shared__ double sb[256];
    sa[t] = acc; sb[t] = h;
    __syncthreads();
    for (int o = 128; o; o >>= 1) {
        if (t < o) { sa[t] += sa[t + o]; sb[t] += sb[t + o]; }
        __syncthreads();
    }
    if (t == 0) {
        out[0] = (float)sb[0];
        out[1] = (float)(sa[0] / (double)BB);
    }
}

// ---------------- host ----------------
extern "C" void kernel_launch(void* const* d_in, const int* in_sizes, int n_in,
                              void* d_out, int out_size)
{
    const float* x1 = (const float*)d_in[0];
    const float* x2 = (const float*)d_in[1];
    const float* x3 = (const float*)d_in[2];
    const float* x4 = (const float*)d_in[3];
    float* out = (float*)d_out;

    cudaFuncSetAttribute(k_simgemm, cudaFuncAttributeMaxDynamicSharedMemorySize, SIM_SMEM);
    cudaFuncSetAttribute(k_hinge,   cudaFuncAttributeMaxDynamicSharedMemorySize, SIM_SMEM);

    float *p0, *p1, *p2, *p3;
    cudaGetSymbolAddress((void**)&p0, d_du0);
    cudaGetSymbolAddress((void**)&p1, d_du1);
    cudaGetSymbolAddress((void**)&p2, d_du2);
    cudaGetSymbolAddress((void**)&p3, d_du3);

    k_normalize<<<2*BB*NT/8, 256>>>(x1, x2, x3, x4);
    k_simgemm<<<dim3(7, 7, BB), 256, SIM_SMEM>>>();
    k_sums<<<(2*BB*NT + 255)/256, 256>>>();
    k_cost<<<dim3(8, 8, BB), 256>>>();
    k_hinge<<<dim3(3, 3, BB), 256, SIM_SMEM>>>(x3, x4);

    const float EPS[8] = {9.0f, 9.0f, 2.25f, 0.5625f, 0.140625f,
                          0.03515625f, 0.0087890625f, 0.0025f};

    // init: f = softmin(eps0, C, 0); g = softmin(eps0, C^T, 0)
    k_softmin_pair<<<2*BB*NR/8, 256>>>(nullptr, nullptr, nullptr, nullptr,
                                       p0, p1, 9.0f, 1.0f/9.0f, 0);

    float *fc = p0, *gc = p1, *fa = p2, *ga = p3;
    for (int k = 0; k < 8; k++) {
        float e = EPS[k], ie = 1.0f / e;
        k_softmin_pair<<<2*BB*NR/8, 256>>>(gc, fc, fc, gc, fa, ga, e, ie, 1);
        float* tf = fc; fc = fa; fa = tf;
        float* tg = gc; gc = ga; ga = tg;
    }
    // final extrapolation at eps = 0.0025 into d_du2/d_du3
    k_softmin_pair<<<2*BB*NR/8, 256>>>(gc, fc, nullptr, nullptr, p2, p3,
                                       0.0025f, 400.0f, 0);

    k_finalize<<<1, 256>>>(out);
}

// round 7
// speedup vs baseline: 3.4715x; 1.6023x over previous
#include <cuda_runtime.h>
#include <cstdint>
#include <mma.h>
#include <math.h>

using namespace nvcuda;

#define BB 16      // batch
#define NR 512     // real points
#define NP 384     // padding points
#define NT 896     // total points per side
#define DD 256     // feature dim

// ---------------- scratch ----------------
__device__ float d_f1n[BB*NT*DD];       // normalized f1 (tf32-rounded)
__device__ float d_f2n[BB*NT*DD];       // normalized f2 (tf32-rounded)
__device__ float d_x3r[BB*NP*DD];       // tf32-rounded raw x3
__device__ float d_x4r[BB*NP*DD];       // tf32-rounded raw x4
__device__ float d_S  [BB*NR*NR];       // S then C (in-place)
__device__ float d_CT [BB*NR*NR];       // C transposed
__device__ float d_srp[BB*7*NT];
__device__ float d_scp[BB*7*NT];
__device__ float d_sr[BB*NT];
__device__ float d_sc[BB*NT];
__device__ float d_du0[BB*NR];
__device__ float d_du1[BB*NR];
__device__ float d_du2[BB*NR];
__device__ float d_du3[BB*NR];
__device__ float d_hpart[144];

// ---------------- FMA-only helpers ----------------
__device__ __forceinline__ float fexp(float x) {
    x = fmaxf(x, -87.0f);
    const float L2E_HI = 1.4426950216293335f;
    const float L2E_LO = 1.9259630e-8f;
    float y = fmaf(x, L2E_HI, 12582912.0f);
    int   n = __float_as_int(y) - 0x4B400000;
    float fi = y - 12582912.0f;
    float r = fmaf(x, L2E_HI, -fi);
    r = fmaf(x, L2E_LO, r);
    float t = r * 0.69314718055994531f;
    float p = 1.3888889e-3f;
    p = fmaf(p, t, 8.3333333e-3f);
    p = fmaf(p, t, 4.1666667e-2f);
    p = fmaf(p, t, 1.6666667e-1f);
    p = fmaf(p, t, 0.5f);
    p = fmaf(p, t, 1.0f);
    p = fmaf(p, t, 1.0f);
    return p * __int_as_float((n + 127) << 23);
}

__device__ __forceinline__ float frcp(float x) {
    float r = __int_as_float(0x7EF311C3 - __float_as_int(x));
    r = r * fmaf(-x, r, 2.0f);
    r = r * fmaf(-x, r, 2.0f);
    r = r * fmaf(-x, r, 2.0f);
    return r;
}

__device__ __forceinline__ void cp16(void* s, const void* g) {
    unsigned int sa = (unsigned int)__cvta_generic_to_shared(s);
    asm volatile("cp.async.cg.shared.global [%0], [%1], 16;" :: "r"(sa), "l"(g));
}

__device__ __forceinline__ float4 tf32x4(float4 v) {
    v.x = wmma::__float_to_tf32(v.x);
    v.y = wmma::__float_to_tf32(v.y);
    v.z = wmma::__float_to_tf32(v.z);
    v.w = wmma::__float_to_tf32(v.w);
    return v;
}

// ---------------- 1) normalize + tf32-round; also emit rounded raw x3/x4 ----------------
__global__ void __launch_bounds__(256) k_normalize(
    const float* __restrict__ x1, const float* __restrict__ x2,
    const float* __restrict__ x3, const float* __restrict__ x4)
{
    int gw   = blockIdx.x * 8 + (threadIdx.x >> 5);
    int lane = threadIdx.x & 31;
    int which = (gw >= BB*NT) ? 1 : 0;
    int r     = which ? gw - BB*NT : gw;
    int b = r / NT, i = r % NT;
    const float* src;
    float* rawdst = nullptr;
    if (i < NR) {
        src = (which ? x2 : x1) + ((size_t)(b*NR + i)) * DD;
    } else {
        size_t off = ((size_t)(b*NP + (i - NR))) * DD;
        src = (which ? x4 : x3) + off;
        rawdst = (which ? d_x4r : d_x3r) + off;
    }
    float* dst = (which ? d_f2n : d_f1n) + (size_t)r * DD;

    float4 v0 = *(const float4*)(src + lane*4);
    float4 v1 = *(const float4*)(src + 128 + lane*4);
    if (rawdst) {   // tf32-RN rounded raw copy for hinge GEMM
        *(float4*)(rawdst + lane*4)       = tf32x4(v0);
        *(float4*)(rawdst + 128 + lane*4) = tf32x4(v1);
    }
    float sq = v0.x*v0.x + v0.y*v0.y + v0.z*v0.z + v0.w*v0.w
             + v1.x*v1.x + v1.y*v1.y + v1.z*v1.z + v1.w*v1.w;
    #pragma unroll
    for (int o = 16; o; o >>= 1) sq += __shfl_xor_sync(0xffffffffu, sq, o);
    float rn = 1.0f / fmaxf(sqrtf(sq), 1e-12f);
    v0.x *= rn; v0.y *= rn; v0.z *= rn; v0.w *= rn;
    v1.x *= rn; v1.y *= rn; v1.z *= rn; v1.w *= rn;
    *(float4*)(dst + lane*4)       = tf32x4(v0);
    *(float4*)(dst + 128 + lane*4) = tf32x4(v1);
}

// ---------------- 2) pipelined tf32 GEMM + exp + partial sums ----------------
#define LDA 36                // ≡4 mod 32 -> conflict-free fragment loads
#define LDE 132
#define STAGE (128*LDA)       // 4608 floats
#define SIM_SMEM (4*STAGE*4)  // 73728 bytes

__global__ void __launch_bounds__(256) k_simgemm()
{
    extern __shared__ float sh[];
    __shared__ float colacc[128];

    int b  = blockIdx.z;
    int m0 = blockIdx.y * 128, n0 = blockIdx.x * 128;
    if (m0 >= NR && n0 >= NR) return;   // padding x padding: feeds nothing

    const float* Ag = d_f1n + (size_t)b * NT * DD + (size_t)m0 * DD;
    const float* Bg = d_f2n + (size_t)b * NT * DD + (size_t)n0 * DD;

    int tid = threadIdx.x;
    int wid = tid >> 5;
    int warp_m = wid >> 2;
    int warp_n = wid & 3;

    wmma::fragment<wmma::accumulator,16,16,8,float> acc[4][2];
    #pragma unroll
    for (int mt = 0; mt < 4; mt++)
        #pragma unroll
        for (int nt = 0; nt < 2; nt++)
            wmma::fill_fragment(acc[mt][nt], 0.0f);

    int lrow = tid >> 3;
    int lc4  = (tid & 7) * 4;

    {
        float* A = sh; float* B = sh + STAGE;
        #pragma unroll
        for (int u = 0; u < 4; u++) {
            int row = lrow + 32*u;
            cp16(&A[row*LDA + lc4], Ag + (size_t)row*DD + lc4);
            cp16(&B[row*LDA + lc4], Bg + (size_t)row*DD + lc4);
        }
        asm volatile("cp.async.commit_group;");
    }

    for (int kc = 0; kc < 8; kc++) {
        if (kc < 7) {
            float* A = sh + ((kc+1)&1)*2*STAGE;
            float* B = A + STAGE;
            int k0 = (kc+1)*32;
            #pragma unroll
            for (int u = 0; u < 4; u++) {
                int row = lrow + 32*u;
                cp16(&A[row*LDA + lc4], Ag + (size_t)row*DD + k0 + lc4);
                cp16(&B[row*LDA + lc4], Bg + (size_t)row*DD + k0 + lc4);
            }
            asm volatile("cp.async.commit_group;");
            asm volatile("cp.async.wait_group 1;");
        } else {
            asm volatile("cp.async.wait_group 0;");
        }
        __syncthreads();
        const float* A = sh + (kc&1)*2*STAGE;
        const float* B = A + STAGE;
        #pragma unroll
        for (int ks = 0; ks < 4; ks++) {
            wmma::fragment<wmma::matrix_b,16,16,8,wmma::precision::tf32,wmma::col_major> bf[2];
            #pragma unroll
            for (int nt = 0; nt < 2; nt++)
                wmma::load_matrix_sync(bf[nt], &B[(warp_n*32 + nt*16)*LDA + ks*8], LDA);
            #pragma unroll
            for (int mt = 0; mt < 4; mt++) {
                wmma::fragment<wmma::matrix_a,16,16,8,wmma::precision::tf32,wmma::row_major> af;
                wmma::load_matrix_sync(af, &A[(warp_m*64 + mt*16)*LDA + ks*8], LDA);
                #pragma unroll
                for (int nt = 0; nt < 2; nt++)
                    wmma::mma_sync(acc[mt][nt], af, bf[nt], acc[mt][nt]);
            }
        }
        __syncthreads();
    }

    if (tid < 128) colacc[tid] = 0.f;
    __syncthreads();

    bool inblk = (m0 < NR) && (n0 < NR);
    int r   = tid >> 2;
    int seg = tid & 3;

    #pragma unroll
    for (int phase = 0; phase < 2; phase++) {
        if (warp_m == phase) {
            #pragma unroll
            for (int mt = 0; mt < 4; mt++)
                #pragma unroll
                for (int nt = 0; nt < 2; nt++)
                    wmma::store_matrix_sync(&sh[(mt*16)*LDE + warp_n*32 + nt*16],
                                            acc[mt][nt], LDE, wmma::mem_row_major);
        }
        __syncthreads();

        int ig = m0 + phase*64 + r;
        float rsum = 0.f;
        float* Srow = d_S + ((size_t)b*NR + ig)*NR + n0 + seg*32;
        #pragma unroll
        for (int q = 0; q < 8; q++) {
            float4 v4 = *(float4*)&sh[r*LDE + seg*32 + q*4];
            v4.x = fexp(10.0f * v4.x);
            v4.y = fexp(10.0f * v4.y);
            v4.z = fexp(10.0f * v4.z);
            v4.w = fexp(10.0f * v4.w);
            rsum += (v4.x + v4.y) + (v4.z + v4.w);
            *(float4*)&sh[r*LDE + seg*32 + q*4] = v4;
            if (inblk) *(float4*)(Srow + q*4) = v4;
        }
        rsum += __shfl_down_sync(0xffffffffu, rsum, 2);
        rsum += __shfl_down_sync(0xffffffffu, rsum, 1);
        if (seg == 0) d_srp[((size_t)b*7 + (n0 >> 7))*NT + ig] = rsum;
        __syncthreads();

        int col  = tid >> 1;
        int half = tid & 1;
        float cs = 0.f;
        #pragma unroll
        for (int rr = 0; rr < 32; rr++)
            cs += sh[(half*32 + rr)*LDE + col];
        cs += __shfl_down_sync(0xffffffffu, cs, 1);
        if (half == 0) colacc[col] += cs;
        __syncthreads();
    }
    if (tid < 128) d_scp[((size_t)b*7 + (m0 >> 7))*NT + n0 + tid] = colacc[tid];
}

// ---------------- 3) reduce partial sums (real rows/cols only) ----------------
__global__ void k_sums()
{
    int idx = blockIdx.x * 256 + threadIdx.x;   // 2*BB*NR
    if (idx >= 2*BB*NR) return;
    int which = idx >= BB*NR;
    int r = which ? idx - BB*NR : idx;
    int b = r >> 9, i = r & 511;
    const float* P = (which ? d_scp : d_srp) + (size_t)b*7*NT + i;
    float s = 0.f;
    #pragma unroll
    for (int t = 0; t < 7; t++) s += P[(size_t)t*NT];
    (which ? d_sc : d_sr)[b*NT + i] = s;
}

// ---------------- 4) cost: C = 1 - s/(sc+sr-s) in-place + C^T ----------------
__global__ void k_cost()
{
    int b  = blockIdx.z;
    int j0 = blockIdx.x * 32, i0 = blockIdx.y * 32;
    float* S  = d_S  + (size_t)b * NR * NR;
    float* CT = d_CT + (size_t)b * NR * NR;
    __shared__ float tile[32][33];
    int tx = threadIdx.x, ty = threadIdx.y;   // (32, 8)
    int j = j0 + tx;
    float scv = d_sc[b * NT + j];
    #pragma unroll
    for (int r = 0; r < 4; r++) {
        int i = i0 + ty + 8*r;
        float s   = S[(size_t)i * NR + j];
        float den = scv + d_sr[b * NT + i] - s;
        float c   = fmaf(-s, frcp(den), 1.0f);
        S[(size_t)i * NR + j] = c;
        tile[ty + 8*r][tx] = c;
    }
    __syncthreads();
    #pragma unroll
    for (int r = 0; r < 4; r++) {
        int ii = j0 + ty + 8*r;
        int jj = i0 + tx;
        CT[(size_t)ii * NR + jj] = tile[tx][ty + 8*r];
    }
}

// ---------------- 5) softmin: warp per row, shfl-only ----------------
__global__ void __launch_bounds__(256) k_softmin_pair(
    const float* __restrict__ hf, const float* __restrict__ hg,
    const float* __restrict__ oldf, const float* __restrict__ oldg,
    float* __restrict__ outf, float* __restrict__ outg,
    float eps, float inv_eps, int avg)
{
    int gw   = blockIdx.x * 8 + (threadIdx.x >> 5);
    int lane = threadIdx.x & 31;
    int side = (gw >= BB*NR) ? 1 : 0;
    int row  = side ? gw - BB*NR : gw;
    int b    = row >> 9;
    const float* Crow = (side ? d_CT : d_S) + (size_t)row * NR;
    const float* hv   = side ? hg : hf;
    const float* oldv = side ? oldg : oldf;
    float*       ov   = side ? outg : outf;
    const float* hb   = hv ? hv + (b << 9) : nullptr;

    float a[16];
    #pragma unroll
    for (int q = 0; q < 4; q++) {
        int j = q*128 + lane*4;
        float4 c4 = *(const float4*)(Crow + j);
        if (hb) {
            float4 h4 = *(const float4*)(hb + j);
            a[q*4+0] = (h4.x - c4.x) * inv_eps;
            a[q*4+1] = (h4.y - c4.y) * inv_eps;
            a[q*4+2] = (h4.z - c4.z) * inv_eps;
            a[q*4+3] = (h4.w - c4.w) * inv_eps;
        } else {
            a[q*4+0] = -c4.x * inv_eps;
            a[q*4+1] = -c4.y * inv_eps;
            a[q*4+2] = -c4.z * inv_eps;
            a[q*4+3] = -c4.w * inv_eps;
        }
    }
    float m = a[0];
    #pragma unroll
    for (int u = 1; u < 16; u++) m = fmaxf(m, a[u]);
    #pragma unroll
    for (int o = 16; o; o >>= 1) m = fmaxf(m, __shfl_xor_sync(0xffffffffu, m, o));
    float s = 0.f;
    #pragma unroll
    for (int u = 0; u < 16; u++) s += fexp(a[u] - m);
    #pragma unroll
    for (int o = 16; o; o >>= 1) s += __shfl_xor_sync(0xffffffffu, s, o);
    if (lane == 0) {
        float val = -eps * (m + logf(s));
        if (avg) val = 0.5f * (oldv[row] + val);
        ov[row] = val;
    }
}

// ---------------- 6) hinge GEMM (pipelined tf32, pre-rounded inputs) ----------------
__global__ void __launch_bounds__(256) k_hinge()
{
    extern __shared__ float sh[];
    int b  = blockIdx.z;
    int m0 = blockIdx.y * 128, n0 = blockIdx.x * 128;
    const float* Ag = d_x3r + (size_t)b * NP * DD + (size_t)m0 * DD;
    const float* Bg = d_x4r + (size_t)b * NP * DD + (size_t)n0 * DD;

    int tid = threadIdx.x;
    int wid = tid >> 5;
    int warp_m = wid >> 2;
    int warp_n = wid & 3;

    wmma::fragment<wmma::accumulator,16,16,8,float> acc[4][2];
    #pragma unroll
    for (int mt = 0; mt < 4; mt++)
        #pragma unroll
        for (int nt = 0; nt < 2; nt++)
            wmma::fill_fragment(acc[mt][nt], 0.0f);

    int lrow = tid >> 3;
    int lc4  = (tid & 7) * 4;

    {
        float* A = sh; float* B = sh + STAGE;
        #pragma unroll
        for (int u = 0; u < 4; u++) {
            int row = lrow + 32*u;
            cp16(&A[row*LDA + lc4], Ag + (size_t)row*DD + lc4);
            cp16(&B[row*LDA + lc4], Bg + (size_t)row*DD + lc4);
        }
        asm volatile("cp.async.commit_group;");
    }

    for (int kc = 0; kc < 8; kc++) {
        if (kc < 7) {
            float* A = sh + ((kc+1)&1)*2*STAGE;
            float* B = A + STAGE;
            int k0 = (kc+1)*32;
            #pragma unroll
            for (int u = 0; u < 4; u++) {
                int row = lrow + 32*u;
                cp16(&A[row*LDA + lc4], Ag + (size_t)row*DD + k0 + lc4);
                cp16(&B[row*LDA + lc4], Bg + (size_t)row*DD + k0 + lc4);
            }
            asm volatile("cp.async.commit_group;");
            asm volatile("cp.async.wait_group 1;");
        } else {
            asm volatile("cp.async.wait_group 0;");
        }
        __syncthreads();
        const float* A = sh + (kc&1)*2*STAGE;
        const float* B = A + STAGE;
        #pragma unroll
        for (int ks = 0; ks < 4; ks++) {
            wmma::fragment<wmma::matrix_b,16,16,8,wmma::precision::tf32,wmma::col_major> bf[2];
            #pragma unroll
            for (int nt = 0; nt < 2; nt++)
                wmma::load_matrix_sync(bf[nt], &B[(warp_n*32 + nt*16)*LDA + ks*8], LDA);
            #pragma unroll
            for (int mt = 0; mt < 4; mt++) {
                wmma::fragment<wmma::matrix_a,16,16,8,wmma::precision::tf32,wmma::row_major> af;
                wmma::load_matrix_sync(af, &A[(warp_m*64 + mt*16)*LDA + ks*8], LDA);
                #pragma unroll
                for (int nt = 0; nt < 2; nt++)
                    wmma::mma_sync(acc[mt][nt], af, bf[nt], acc[mt][nt]);
            }
        }
        __syncthreads();
    }

    float loc = 0.f;
    #pragma unroll
    for (int mt = 0; mt < 4; mt++)
        #pragma unroll
        for (int nt = 0; nt < 2; nt++)
            #pragma unroll
            for (int e = 0; e < acc[mt][nt].num_elements; e++)
                loc += fmaxf(0.1f - acc[mt][nt].x[e], 0.0f);

    __shared__ float red[8];
    #pragma unroll
    for (int o = 16; o; o >>= 1) loc += __shfl_xor_sync(0xffffffffu, loc, o);
    if ((tid & 31) == 0) red[tid >> 5] = loc;
    __syncthreads();
    if (tid == 0) {
        float tot = 0.f;
        #pragma unroll
        for (int w = 0; w < 8; w++) tot += red[w];
        d_hpart[blockIdx.z * 9 + blockIdx.y * 3 + blockIdx.x] = tot;
    }
}

// ---------------- 7) deterministic final reduction ----------------
__global__ void k_finalize(float* __restrict__ out)
{
    int t = threadIdx.x;
    double acc = 0.0;
    for (int idx = t; idx < BB*NR; idx += 256)
        acc += (double)d_du2[idx] + (double)d_du3[idx];
    double h = 0.0;
    for (int idx = t; idx < 144; idx += 256) h += (double)d_hpart[idx];
    __shared__ double sa[256];
    __shared__ double sb[256];
    sa[t] = acc; sb[t] = h;
    __syncthreads();
    for (int o = 128; o; o >>= 1) {
        if (t < o) { sa[t] += sa[t + o]; sb[t] += sb[t + o]; }
        __syncthreads();
    }
    if (t == 0) {
        out[0] = (float)sb[0];
        out[1] = (float)(sa[0] / (double)BB);
    }
}

// ---------------- host ----------------
extern "C" void kernel_launch(void* const* d_in, const int* in_sizes, int n_in,
                              void* d_out, int out_size)
{
    const float* x1 = (const float*)d_in[0];
    const float* x2 = (const float*)d_in[1];
    const float* x3 = (const float*)d_in[2];
    const float* x4 = (const float*)d_in[3];
    float* out = (float*)d_out;

    cudaFuncSetAttribute(k_simgemm, cudaFuncAttributeMaxDynamicSharedMemorySize, SIM_SMEM);
    cudaFuncSetAttribute(k_hinge,   cudaFuncAttributeMaxDynamicSharedMemorySize, SIM_SMEM);

    float *p0, *p1, *p2, *p3;
    cudaGetSymbolAddress((void**)&p0, d_du0);
    cudaGetSymbolAddress((void**)&p1, d_du1);
    cudaGetSymbolAddress((void**)&p2, d_du2);
    cudaGetSymbolAddress((void**)&p3, d_du3);

    k_normalize<<<2*BB*NT/8, 256>>>(x1, x2, x3, x4);
    k_simgemm<<<dim3(7, 7, BB), 256, SIM_SMEM>>>();
    k_sums<<<(2*BB*NR + 255)/256, 256>>>();
    k_cost<<<dim3(NR/32, NR/32, BB), dim3(32, 8)>>>();
    k_hinge<<<dim3(3, 3, BB), 256, SIM_SMEM>>>();

    const float EPS[8] = {9.0f, 9.0f, 2.25f, 0.5625f, 0.140625f,
                          0.03515625f, 0.0087890625f, 0.0025f};

    k_softmin_pair<<<2*BB*NR/8, 256>>>(nullptr, nullptr, nullptr, nullptr,
                                       p0, p1, 9.0f, 1.0f/9.0f, 0);

    float *fc = p0, *gc = p1, *fa = p2, *ga = p3;
    for (int k = 0; k < 8; k++) {
        float e = EPS[k], ie = 1.0f / e;
        k_softmin_pair<<<2*BB*NR/8, 256>>>(gc, fc, fc, gc, fa, ga, e, ie, 1);
        float* tf = fc; fc = fa; fa = tf;
        float* tg = gc; gc = ga; ga = tg;
    }
    k_softmin_pair<<<2*BB*NR/8, 256>>>(gc, fc, nullptr, nullptr, p2, p3,
                                       0.0025f, 400.0f, 0);

    k_finalize<<<1, 256>>>(out);
}